// round 2
// baseline (speedup 1.0000x reference)
#include <cuda_runtime.h>
#include <math.h>

// Problem constants
constexpr int Bn  = 4;
constexpr int C   = 64;     // CIN == COUT
constexpr int H   = 192;
constexpr int Wd  = 192;

// Tiling
constexpr int TH  = 16;
constexpr int TW  = 16;
constexpr int HP  = TH + 2;       // 18 (halo rows)
constexpr int WP  = TW + 2;       // 18 (halo cols)
constexpr int NPT = HP * WP;      // 324 halo points
constexpr int OC  = 8;            // output channels per chunk
constexpr int BDIM = 256;

// Shared memory layout (floats):
//  xs  [C][NPT]      : x halo tile (reflection applied)
//  ks  [OC][NPT]     : k for current channel chunk
//  vs  [OC][NPT]     : v for current channel chunk
//  wks/wvs/wqs [OC][64]
//  bss [3*OC]        : bk | bv | bq for chunk
constexpr int SM_FLOATS = C*NPT + 2*OC*NPT + 3*OC*64 + 3*OC;

__global__ __launch_bounds__(BDIM, 2)
void attn_kernel(const float* __restrict__ x,
                 const float* __restrict__ Wq, const float* __restrict__ bq,
                 const float* __restrict__ Wk, const float* __restrict__ bk,
                 const float* __restrict__ Wv, const float* __restrict__ bv,
                 float* __restrict__ out)
{
    extern __shared__ float sm[];
    float* xs  = sm;                    // C*NPT
    float* ks  = xs  + C*NPT;           // OC*NPT
    float* vs  = ks  + OC*NPT;          // OC*NPT
    float* wks = vs  + OC*NPT;          // OC*64
    float* wvs = wks + OC*64;           // OC*64
    float* wqs = wvs + OC*64;           // OC*64
    float* bss = wqs + OC*64;           // 3*OC

    const int b   = blockIdx.z;
    const int h0  = blockIdx.y * TH;
    const int w0  = blockIdx.x * TW;
    const int tid = threadIdx.x;

    // ------------------------------------------------------------------
    // Phase 0: load x halo tile into smem with reflection pad(1) applied.
    // Reflect: padded coord -1 -> 1, H -> H-2 (jnp.pad mode="reflect").
    // ------------------------------------------------------------------
    const float* xb = x + (size_t)b * C * H * Wd;
    for (int i = tid; i < C * NPT; i += BDIM) {
        int c  = i / NPT;
        int p  = i - c * NPT;
        int py = p / WP;
        int px = p - py * WP;
        int gy = h0 + py - 1;
        gy = (gy < 0) ? -gy : ((gy >= H) ? (2*H - 2 - gy) : gy);
        int gx = w0 + px - 1;
        gx = (gx < 0) ? -gx : ((gx >= Wd) ? (2*Wd - 2 - gx) : gx);
        xs[i] = xb[c * H * Wd + gy * Wd + gx];
    }
    __syncthreads();

    const int ty = tid >> 4;            // 0..15
    const int tx = tid & 15;            // 0..15
    const int ip = (ty + 1) * WP + (tx + 1);   // my interior halo index
    float* outp = out + (((size_t)b * C) * H + (h0 + ty)) * Wd + (w0 + tx);

    // ------------------------------------------------------------------
    // Channel-chunk loop
    // ------------------------------------------------------------------
    for (int c0 = 0; c0 < C; c0 += OC) {
        // Load this chunk's weights + biases into smem
        for (int i = tid; i < OC * 64; i += BDIM) {
            int r = i >> 6;
            int c = i & 63;
            wks[i] = Wk[(c0 + r) * C + c];
            wvs[i] = Wv[(c0 + r) * C + c];
            wqs[i] = Wq[(c0 + r) * C + c];
        }
        if (tid < OC) {
            bss[tid]        = bk[c0 + tid];
            bss[OC + tid]   = bv[c0 + tid];
            bss[2*OC + tid] = bq[c0 + tid];
        }
        __syncthreads();

        // ---- k/v for all 324 halo points, OC channels ----
        for (int p = tid; p < NPT; p += BDIM) {
            float aK[OC], aV[OC];
            #pragma unroll
            for (int r = 0; r < OC; ++r) { aK[r] = bss[r]; aV[r] = bss[OC + r]; }

            #pragma unroll 4
            for (int c = 0; c < C; c += 4) {
                float x0 = xs[(c + 0) * NPT + p];
                float x1 = xs[(c + 1) * NPT + p];
                float x2 = xs[(c + 2) * NPT + p];
                float x3 = xs[(c + 3) * NPT + p];
                #pragma unroll
                for (int r = 0; r < OC; ++r) {
                    float4 k4 = *reinterpret_cast<const float4*>(wks + r * 64 + c);
                    float4 v4 = *reinterpret_cast<const float4*>(wvs + r * 64 + c);
                    aK[r] = fmaf(k4.x, x0, aK[r]);
                    aK[r] = fmaf(k4.y, x1, aK[r]);
                    aK[r] = fmaf(k4.z, x2, aK[r]);
                    aK[r] = fmaf(k4.w, x3, aK[r]);
                    aV[r] = fmaf(v4.x, x0, aV[r]);
                    aV[r] = fmaf(v4.y, x1, aV[r]);
                    aV[r] = fmaf(v4.z, x2, aV[r]);
                    aV[r] = fmaf(v4.w, x3, aV[r]);
                }
            }
            #pragma unroll
            for (int r = 0; r < OC; ++r) {
                ks[r * NPT + p] = aK[r];
                vs[r * NPT + p] = aV[r];
            }
        }
        __syncthreads();

        // ---- q + 9-tap per-channel softmax for my pixel ----
        #pragma unroll 1
        for (int r = 0; r < OC; ++r) {
            // q = bq + Wq[r] . x[:, my pixel]   (4 partial accumulators for ILP)
            const float* wq_r = wqs + r * 64;
            float q0 = bss[2*OC + r], q1 = 0.f, q2 = 0.f, q3 = 0.f;
            #pragma unroll 4
            for (int c = 0; c < C; c += 4) {
                float4 w4 = *reinterpret_cast<const float4*>(wq_r + c);
                q0 = fmaf(w4.x, xs[(c + 0) * NPT + ip], q0);
                q1 = fmaf(w4.y, xs[(c + 1) * NPT + ip], q1);
                q2 = fmaf(w4.z, xs[(c + 2) * NPT + ip], q2);
                q3 = fmaf(w4.w, xs[(c + 3) * NPT + ip], q3);
            }
            float q = (q0 + q1) + (q2 + q3);

            const float* kr = ks + r * NPT;
            const float* vr = vs + r * NPT;
            const int base = ty * WP + tx;   // top-left tap

            float l[9];
            #pragma unroll
            for (int j = 0; j < 9; ++j) {
                int pp = base + (j / 3) * WP + (j % 3);
                l[j] = q * kr[pp];
            }
            float m = l[0];
            #pragma unroll
            for (int j = 1; j < 9; ++j) m = fmaxf(m, l[j]);

            float s = 0.f, acc = 0.f;
            #pragma unroll
            for (int j = 0; j < 9; ++j) {
                int pp = base + (j / 3) * WP + (j % 3);
                float e = __expf(l[j] - m);
                s   += e;
                acc  = fmaf(e, vr[pp], acc);
            }
            outp[(size_t)(c0 + r) * H * Wd] = acc / s;
        }
        __syncthreads();
    }
}

extern "C" void kernel_launch(void* const* d_in, const int* in_sizes, int n_in,
                              void* d_out, int out_size)
{
    const float* x  = (const float*)d_in[0];
    const float* Wq = (const float*)d_in[1];
    const float* bq = (const float*)d_in[2];
    const float* Wk = (const float*)d_in[3];
    const float* bk = (const float*)d_in[4];
    const float* Wv = (const float*)d_in[5];
    const float* bv = (const float*)d_in[6];
    float* out = (float*)d_out;

    const int smem_bytes = SM_FLOATS * (int)sizeof(float);   // ~110 KB
    cudaFuncSetAttribute(attn_kernel, cudaFuncAttributeMaxDynamicSharedMemorySize,
                         smem_bytes);

    dim3 grid(Wd / TW, H / TH, Bn);   // (12, 12, 4)
    attn_kernel<<<grid, BDIM, smem_bytes>>>(x, Wq, bq, Wk, bk, Wv, bv, out);
}

// round 3
// speedup vs baseline: 1.6986x; 1.6986x over previous
#include <cuda_runtime.h>
#include <math.h>

// Problem constants
constexpr int Bn  = 4;
constexpr int C   = 64;     // CIN == COUT
constexpr int H   = 192;
constexpr int Wd  = 192;

// Tiling
constexpr int TH   = 16;
constexpr int TW   = 16;
constexpr int HP   = TH + 2;        // 18
constexpr int WP   = TW + 2;        // 18
constexpr int NPT  = HP * WP;       // 324 halo points  (324 = 81*4, exact float4 split)
constexpr int NPAD = 328;           // row stride (floats), 16B aligned
constexpr int OC   = 16;            // channels per chunk
constexpr int ROWS = 3 * OC;        // 48 GEMM rows per chunk: [q16 | k16 | v16]
constexpr int BDIM = 512;

// GEMM thread tiling: 8 rows x 4 points per thread
constexpr int RG = ROWS / 8;        // 6 row groups
constexpr int CG = NPT / 4;         // 81 col groups
constexpr int NTILE = RG * CG;      // 486 (<= 512)

// Shared memory (floats)
//  xs   [64][NPAD]    x halo tile, K-major (c outer, point inner)
//  qkv  [48][NPAD]    current chunk outputs
//  wT   [64][48]      transposed weights for chunk
//  bias [48]
constexpr int SM_FLOATS = C * NPAD + ROWS * NPAD + C * ROWS + ROWS;

__global__ __launch_bounds__(BDIM, 1)
void attn_kernel(const float* __restrict__ x,
                 const float* __restrict__ Wq, const float* __restrict__ bq,
                 const float* __restrict__ Wk, const float* __restrict__ bk,
                 const float* __restrict__ Wv, const float* __restrict__ bv,
                 float* __restrict__ out)
{
    extern __shared__ float sm[];
    float* xs   = sm;                        // C*NPAD
    float* qkv  = xs  + C * NPAD;            // ROWS*NPAD
    float* wT   = qkv + ROWS * NPAD;         // C*ROWS
    float* bias = wT  + C * ROWS;            // ROWS

    const int b   = blockIdx.z;
    const int h0  = blockIdx.y * TH;
    const int w0  = blockIdx.x * TW;
    const int tid = threadIdx.x;

    // ------------------------------------------------------------------
    // Phase 0: x halo tile -> smem, reflection pad(1) applied.
    // ------------------------------------------------------------------
    const float* xb = x + (size_t)b * C * H * Wd;
    for (int i = tid; i < C * NPT; i += BDIM) {
        int c  = i / NPT;
        int p  = i - c * NPT;
        int py = p / WP;
        int px = p - py * WP;
        int gy = h0 + py - 1;
        gy = (gy < 0) ? -gy : ((gy >= H) ? (2 * H - 2 - gy) : gy);
        int gx = w0 + px - 1;
        gx = (gx < 0) ? -gx : ((gx >= Wd) ? (2 * Wd - 2 - gx) : gx);
        xs[c * NPAD + p] = xb[c * H * Wd + gy * Wd + gx];
    }

    // GEMM tile assignment (fixed per thread)
    const int rg = tid / CG;            // 0..5 (tid >= NTILE -> inactive)
    const int cg = tid - rg * CG;       // 0..80
    const bool gemm_active = (tid < NTILE);

    // Softmax-phase assignment: 2 threads per pixel, 8 channels each
    const int px_  = tid & 255;
    const int half = tid >> 8;          // 0 / 1
    const int ty = px_ >> 4;
    const int tx = px_ & 15;
    const int ip   = (ty + 1) * WP + (tx + 1);   // my interior halo point
    const int base = ty * WP + tx;               // top-left tap
    float* outp = out + (((size_t)b * C) * H + (h0 + ty)) * Wd + (w0 + tx);

    const float4* wT4  = reinterpret_cast<const float4*>(wT);
    const float4* xs4  = reinterpret_cast<const float4*>(xs);
    float4*       qkv4 = reinterpret_cast<float4*>(qkv);

    // ------------------------------------------------------------------
    // Channel-chunk loop (4 chunks of 16 channels)
    // ------------------------------------------------------------------
    for (int c0 = 0; c0 < C; c0 += OC) {
        // Phase 1: load transposed weights + biases for this chunk.
        // wT[c][row], row 0..15 = q, 16..31 = k, 32..47 = v (channels c0..c0+15)
        for (int i = tid; i < C * ROWS; i += BDIM) {
            int c   = i / ROWS;
            int row = i - c * ROWS;
            int mat = row >> 4;          // 0=q 1=k 2=v
            int ch  = c0 + (row & 15);
            const float* Wsrc = (mat == 0) ? Wq : (mat == 1) ? Wk : Wv;
            wT[i] = Wsrc[ch * C + c];
        }
        if (tid < ROWS) {
            int mat = tid >> 4;
            int ch  = c0 + (tid & 15);
            const float* bsrc = (mat == 0) ? bq : (mat == 1) ? bk : bv;
            bias[tid] = bsrc[ch];
        }
        __syncthreads();   // wT ready; prev chunk's softmax done reading qkv

        // Phase 2: GEMM  qkv[48][324] = wT^T (48x64) * xs (64x324)
        if (gemm_active) {
            float acc[8][4];
            #pragma unroll
            for (int r = 0; r < 8; ++r) {
                float bv_ = bias[rg * 8 + r];
                acc[r][0] = bv_; acc[r][1] = bv_; acc[r][2] = bv_; acc[r][3] = bv_;
            }
            const int wbase = rg * 2;          // float4 index within a wT row
            #pragma unroll 4
            for (int c = 0; c < C; ++c) {
                float4 wa = wT4[c * (ROWS / 4) + wbase];        // rows rg*8 + 0..3
                float4 wb = wT4[c * (ROWS / 4) + wbase + 1];    // rows rg*8 + 4..7
                float4 xv = xs4[c * (NPAD / 4) + cg];
                acc[0][0] = fmaf(wa.x, xv.x, acc[0][0]);
                acc[0][1] = fmaf(wa.x, xv.y, acc[0][1]);
                acc[0][2] = fmaf(wa.x, xv.z, acc[0][2]);
                acc[0][3] = fmaf(wa.x, xv.w, acc[0][3]);
                acc[1][0] = fmaf(wa.y, xv.x, acc[1][0]);
                acc[1][1] = fmaf(wa.y, xv.y, acc[1][1]);
                acc[1][2] = fmaf(wa.y, xv.z, acc[1][2]);
                acc[1][3] = fmaf(wa.y, xv.w, acc[1][3]);
                acc[2][0] = fmaf(wa.z, xv.x, acc[2][0]);
                acc[2][1] = fmaf(wa.z, xv.y, acc[2][1]);
                acc[2][2] = fmaf(wa.z, xv.z, acc[2][2]);
                acc[2][3] = fmaf(wa.z, xv.w, acc[2][3]);
                acc[3][0] = fmaf(wa.w, xv.x, acc[3][0]);
                acc[3][1] = fmaf(wa.w, xv.y, acc[3][1]);
                acc[3][2] = fmaf(wa.w, xv.z, acc[3][2]);
                acc[3][3] = fmaf(wa.w, xv.w, acc[3][3]);
                acc[4][0] = fmaf(wb.x, xv.x, acc[4][0]);
                acc[4][1] = fmaf(wb.x, xv.y, acc[4][1]);
                acc[4][2] = fmaf(wb.x, xv.z, acc[4][2]);
                acc[4][3] = fmaf(wb.x, xv.w, acc[4][3]);
                acc[5][0] = fmaf(wb.y, xv.x, acc[5][0]);
                acc[5][1] = fmaf(wb.y, xv.y, acc[5][1]);
                acc[5][2] = fmaf(wb.y, xv.z, acc[5][2]);
                acc[5][3] = fmaf(wb.y, xv.w, acc[5][3]);
                acc[6][0] = fmaf(wb.z, xv.x, acc[6][0]);
                acc[6][1] = fmaf(wb.z, xv.y, acc[6][1]);
                acc[6][2] = fmaf(wb.z, xv.z, acc[6][2]);
                acc[6][3] = fmaf(wb.z, xv.w, acc[6][3]);
                acc[7][0] = fmaf(wb.w, xv.x, acc[7][0]);
                acc[7][1] = fmaf(wb.w, xv.y, acc[7][1]);
                acc[7][2] = fmaf(wb.w, xv.z, acc[7][2]);
                acc[7][3] = fmaf(wb.w, xv.w, acc[7][3]);
            }
            #pragma unroll
            for (int r = 0; r < 8; ++r) {
                qkv4[(rg * 8 + r) * (NPAD / 4) + cg] =
                    make_float4(acc[r][0], acc[r][1], acc[r][2], acc[r][3]);
            }
        }
        __syncthreads();   // qkv ready

        // Phase 3: per-pixel, per-channel 9-tap softmax (no max-sub; |q*k| small)
        #pragma unroll 1
        for (int r = 0; r < 8; ++r) {
            const int ch = half * 8 + r;                 // 0..15 within chunk
            const float q = qkv[ch * NPAD + ip];
            const float* kr = qkv + (OC + ch) * NPAD;
            const float* vr = qkv + (2 * OC + ch) * NPAD;

            float s = 0.f, acc = 0.f;
            #pragma unroll
            for (int j = 0; j < 9; ++j) {
                int pp = base + (j / 3) * WP + (j % 3);
                float e = __expf(q * kr[pp]);
                s   += e;
                acc  = fmaf(e, vr[pp], acc);
            }
            outp[(size_t)(c0 + ch) * H * Wd] = __fdividef(acc, s);
        }
        // no sync needed here: next iteration's phase-1 writes only wT/bias,
        // and its trailing __syncthreads orders qkv reuse.
    }
}

extern "C" void kernel_launch(void* const* d_in, const int* in_sizes, int n_in,
                              void* d_out, int out_size)
{
    const float* x  = (const float*)d_in[0];
    const float* Wq = (const float*)d_in[1];
    const float* bq = (const float*)d_in[2];
    const float* Wk = (const float*)d_in[3];
    const float* bk = (const float*)d_in[4];
    const float* Wv = (const float*)d_in[5];
    const float* bv = (const float*)d_in[6];
    float* out = (float*)d_out;

    const int smem_bytes = SM_FLOATS * (int)sizeof(float);   // ~159 KB
    cudaFuncSetAttribute(attn_kernel, cudaFuncAttributeMaxDynamicSharedMemorySize,
                         smem_bytes);

    dim3 grid(Wd / TW, H / TH, Bn);   // (12, 12, 4)
    attn_kernel<<<grid, BDIM, smem_bytes>>>(x, Wq, bq, Wk, bk, Wv, bv, out);
}

// round 5
// speedup vs baseline: 2.3989x; 1.4123x over previous
#include <cuda_runtime.h>
#include <cuda_bf16.h>
#include <math.h>
#include <cstdint>

// ---------------- problem constants ----------------
constexpr int Bn  = 4;
constexpr int C   = 64;      // CIN == COUT
constexpr int H   = 192;
constexpr int Wd  = 192;

// ---------------- tiling ----------------
constexpr int TH   = 16;
constexpr int TW   = 16;
constexpr int WP   = TW + 2;           // 18
constexpr int NPT  = (TH + 2) * WP;    // 324 halo points
constexpr int NB   = 328;              // GEMM N (41 n8 chunks)
constexpr int KT   = 192;              // 3*64 bf16 K (hi|lo split, 3 segments)
constexpr int KPAD = 200;              // Xs/Ws row stride in bf16 (400B, bank-rotating)
constexpr int OC   = 16;               // channels per chunk
constexpr int NPADQ = 330;             // qkv row stride (floats); even -> aligned float2
constexpr int BDIM = 512;

// ---------------- smem layout (bytes) ----------------
constexpr int OFF_X    = 0;                          // NB*KPAD*2   = 131200
constexpr int OFF_W    = OFF_X + NB * KPAD * 2;      // 48*KPAD*2   = 19200
constexpr int OFF_BIAS = OFF_W + 48 * KPAD * 2;      // 48*4        = 192
constexpr int OFF_QKV  = OFF_BIAS + 256;             // 48*330*4    = 63360
constexpr int SMEM_TOTAL = OFF_QKV + 48 * NPADQ * 4; // 214208

__device__ __forceinline__ void mma16816(float* c, const uint32_t* a, const uint32_t* b) {
    asm volatile(
        "mma.sync.aligned.m16n8k16.row.col.f32.bf16.bf16.f32 "
        "{%0,%1,%2,%3}, {%4,%5,%6,%7}, {%8,%9}, {%0,%1,%2,%3};"
        : "+f"(c[0]), "+f"(c[1]), "+f"(c[2]), "+f"(c[3])
        : "r"(a[0]), "r"(a[1]), "r"(a[2]), "r"(a[3]), "r"(b[0]), "r"(b[1]));
}

__device__ __forceinline__ uint32_t pack_bf16x2(float lo_f, float hi_f) {
    __nv_bfloat162 h = __floats2bfloat162_rn(lo_f, hi_f);
    return *reinterpret_cast<uint32_t*>(&h);
}

__global__ __launch_bounds__(BDIM, 1)
void attn_kernel(const float* __restrict__ x,
                 const float* __restrict__ Wq, const float* __restrict__ bq,
                 const float* __restrict__ Wk, const float* __restrict__ bk,
                 const float* __restrict__ Wv, const float* __restrict__ bv,
                 float* __restrict__ out)
{
    extern __shared__ char smem[];
    __nv_bfloat16* Xs = reinterpret_cast<__nv_bfloat16*>(smem + OFF_X);   // [NB][KPAD]
    __nv_bfloat16* Ws = reinterpret_cast<__nv_bfloat16*>(smem + OFF_W);   // [48][KPAD]
    float*  bsh = reinterpret_cast<float*>(smem + OFF_BIAS);              // [48]
    float*  qkv = reinterpret_cast<float*>(smem + OFF_QKV);               // [48][NPADQ]

    const int b    = blockIdx.z;
    const int h0   = blockIdx.y * TH;
    const int w0   = blockIdx.x * TW;
    const int tid  = threadIdx.x;
    const int wid  = tid >> 5;
    const int lane = tid & 31;

    // ------------------------------------------------------------------
    // Phase 0: X halo tile -> smem, reflection pad(1), bf16 hi/lo split.
    // Xs row = point, cols: [0:64)=Xhi, [64:128)=Xhi, [128:192)=Xlo.
    // Handle channels in pairs -> 32-bit STS.
    // ------------------------------------------------------------------
    const float* xb = x + (size_t)b * C * H * Wd;
    for (int i = tid; i < (C / 2) * NPT; i += BDIM) {
        int cp = i / NPT;            // channel pair 0..31
        int p  = i - cp * NPT;
        int c  = cp * 2;
        int py = p / WP;
        int px = p - py * WP;
        int gy = h0 + py - 1;
        gy = (gy < 0) ? -gy : ((gy >= H) ? (2 * H - 2 - gy) : gy);
        int gx = w0 + px - 1;
        gx = (gx < 0) ? -gx : ((gx >= Wd) ? (2 * Wd - 2 - gx) : gx);
        float x0 = xb[(c + 0) * H * Wd + gy * Wd + gx];
        float x1 = xb[(c + 1) * H * Wd + gy * Wd + gx];
        __nv_bfloat16 h0b = __float2bfloat16(x0);
        __nv_bfloat16 h1b = __float2bfloat16(x1);
        float l0 = x0 - __bfloat162float(h0b);
        float l1 = x1 - __bfloat162float(h1b);
        uint32_t hi2 = ((uint32_t)*reinterpret_cast<uint16_t*>(&h0b)) |
                       ((uint32_t)*reinterpret_cast<uint16_t*>(&h1b) << 16);
        uint32_t lo2 = pack_bf16x2(l0, l1);
        uint32_t* row = reinterpret_cast<uint32_t*>(Xs + p * KPAD);
        row[c / 2]            = hi2;   // seg0: hi
        row[(64 + c) / 2]     = hi2;   // seg1: hi
        row[(128 + c) / 2]    = lo2;   // seg2: lo
    }
    // zero pad rows 324..327 (cols 0..191)
    for (int i = tid; i < 4 * (KT / 2); i += BDIM) {
        int p = NPT + i / (KT / 2);
        int c2 = i % (KT / 2);
        reinterpret_cast<uint32_t*>(Xs + p * KPAD)[c2] = 0u;
    }

    // softmax-phase fixed assignment: 2 threads/pixel, 8 channels each
    const int px_  = tid & 255;
    const int half = tid >> 8;
    const int ty   = px_ >> 4;
    const int tx   = px_ & 15;
    const int ip   = (ty + 1) * WP + (tx + 1);
    const int tap0 = ty * WP + tx;
    float* outp = out + (((size_t)b * C) * H + (h0 + ty)) * Wd + (w0 + tx);

    // GEMM warp assignment: 12 warps = 3 m-tiles x 4 n-groups
    const int mtile  = wid >> 2;          // 0..3 (3 = inactive)
    const int ngrp   = wid & 3;
    const bool gemm_w = (wid < 12);
    const int r0 = mtile * 16 + (lane >> 2);   // D rows handled by this lane
    const int r1 = r0 + 8;

    // ------------------------------------------------------------------
    // chunk loop: 4 chunks of 16 channels. rows: [q16 | k16 | v16]
    // ------------------------------------------------------------------
    for (int ck = 0; ck < 4; ++ck) {
        const int c0 = ck * OC;

        // Phase A: chunk weights -> Ws (segments: hi | lo | hi), bias -> bsh
        for (int i = tid; i < 48 * 32; i += BDIM) {
            int m  = i >> 5;            // 0..47
            int cp = i & 31;
            int c  = cp * 2;
            int mat = m >> 4;
            int ch  = c0 + (m & 15);
            const float* Wsrc = (mat == 0) ? Wq : (mat == 1) ? Wk : Wv;
            float2 w = *reinterpret_cast<const float2*>(Wsrc + ch * C + c);
            __nv_bfloat16 h0b = __float2bfloat16(w.x);
            __nv_bfloat16 h1b = __float2bfloat16(w.y);
            float l0 = w.x - __bfloat162float(h0b);
            float l1 = w.y - __bfloat162float(h1b);
            uint32_t hi2 = ((uint32_t)*reinterpret_cast<uint16_t*>(&h0b)) |
                           ((uint32_t)*reinterpret_cast<uint16_t*>(&h1b) << 16);
            uint32_t lo2 = pack_bf16x2(l0, l1);
            uint32_t* row = reinterpret_cast<uint32_t*>(Ws + m * KPAD);
            row[c / 2]         = hi2;   // seg0: hi
            row[(64 + c) / 2]  = lo2;   // seg1: lo
            row[(128 + c) / 2] = hi2;   // seg2: hi
        }
        if (tid < 48) {
            int mat = tid >> 4;
            int ch  = c0 + (tid & 15);
            bsh[tid] = ((mat == 0) ? bq : (mat == 1) ? bk : bv)[ch];
        }
        __syncthreads();   // Ws/bias ready; prev softmax done -> qkv reusable

        // Phase B: HMMA GEMM  qkv[48][328] = Ws[48][192] * Xs^T
        if (gemm_w) {
            float acc[11][4];
            {
                float b0v = bsh[r0], b1v = bsh[r1];
                #pragma unroll
                for (int jj = 0; jj < 11; ++jj) {
                    acc[jj][0] = b0v; acc[jj][1] = b0v;
                    acc[jj][2] = b1v; acc[jj][3] = b1v;
                }
            }
            #pragma unroll 1
            for (int s = 0; s < 12; ++s) {
                const int kb = s * 16;                 // k offset (bf16)
                uint32_t a[4];
                {
                    const uint32_t* ar0 = reinterpret_cast<const uint32_t*>(Ws + r0 * KPAD + kb);
                    const uint32_t* ar1 = reinterpret_cast<const uint32_t*>(Ws + r1 * KPAD + kb);
                    int t = lane & 3;
                    a[0] = ar0[t];
                    a[1] = ar1[t];
                    a[2] = ar0[t + 4];
                    a[3] = ar1[t + 4];
                }
                #pragma unroll
                for (int jj = 0; jj < 11; ++jj) {
                    int j = ngrp + jj * 4;
                    if (j < 41) {
                        int n = j * 8 + (lane >> 2);
                        const uint32_t* br = reinterpret_cast<const uint32_t*>(Xs + n * KPAD + kb);
                        uint32_t bfr[2];
                        int t = lane & 3;
                        bfr[0] = br[t];
                        bfr[1] = br[t + 4];
                        mma16816(acc[jj], a, bfr);
                    }
                }
            }
            // store D -> qkv (+0: rows r0, +8: rows r1), cols j*8 + (lane&3)*2
            #pragma unroll
            for (int jj = 0; jj < 11; ++jj) {
                int j = ngrp + jj * 4;
                if (j < 41) {
                    int col = j * 8 + (lane & 3) * 2;
                    *reinterpret_cast<float2*>(qkv + r0 * NPADQ + col) =
                        make_float2(acc[jj][0], acc[jj][1]);
                    *reinterpret_cast<float2*>(qkv + r1 * NPADQ + col) =
                        make_float2(acc[jj][2], acc[jj][3]);
                }
            }
        }
        __syncthreads();   // qkv ready

        // Phase C: per-pixel, per-channel 9-tap softmax
        #pragma unroll 1
        for (int r = 0; r < 8; ++r) {
            const int ch = half * 8 + r;                    // 0..15
            const float q = qkv[ch * NPADQ + ip];
            const float* kr = qkv + (16 + ch) * NPADQ;
            const float* vr = qkv + (32 + ch) * NPADQ;
            float s = 0.f, acc = 0.f;
            #pragma unroll
            for (int t = 0; t < 9; ++t) {
                int pp = tap0 + (t / 3) * WP + (t % 3);
                float e = __expf(q * kr[pp]);
                s   += e;
                acc  = fmaf(e, vr[pp], acc);
            }
            outp[(size_t)(c0 + ch) * H * Wd] = __fdividef(acc, s);
        }
        // next iteration's post-A __syncthreads orders qkv reuse
    }
}

extern "C" void kernel_launch(void* const* d_in, const int* in_sizes, int n_in,
                              void* d_out, int out_size)
{
    const float* x  = (const float*)d_in[0];
    const float* Wq = (const float*)d_in[1];
    const float* bq = (const float*)d_in[2];
    const float* Wk = (const float*)d_in[3];
    const float* bk = (const float*)d_in[4];
    const float* Wv = (const float*)d_in[5];
    const float* bv = (const float*)d_in[6];
    float* out = (float*)d_out;

    cudaFuncSetAttribute(attn_kernel, cudaFuncAttributeMaxDynamicSharedMemorySize,
                         SMEM_TOTAL);
    dim3 grid(Wd / TW, H / TH, Bn);   // (12, 12, 4)
    attn_kernel<<<grid, BDIM, SMEM_TOTAL>>>(x, Wq, bq, Wk, bk, Wv, bv, out);
}

// round 6
// speedup vs baseline: 2.5421x; 1.0597x over previous
#include <cuda_runtime.h>
#include <cuda_bf16.h>
#include <math.h>
#include <cstdint>

// ---------------- problem constants ----------------
constexpr int Bn  = 4;
constexpr int C   = 64;      // CIN == COUT
constexpr int H   = 192;
constexpr int Wd  = 192;

// ---------------- tiling ----------------
constexpr int TH   = 16;
constexpr int TW   = 16;
constexpr int WP   = TW + 2;           // 18
constexpr int NPT  = (TH + 2) * WP;    // 324 halo points
constexpr int NB   = 336;              // GEMM N padded to 21 groups of n16
constexpr int NG   = 21;               // n16 groups
constexpr int KT   = 192;              // 3*64 bf16 K (hi/lo split, 3 segments)
constexpr int KPAD = 200;              // Xs/Ws row stride in bf16 (400B)
constexpr int OC   = 16;               // channels per chunk
constexpr int NPADQ = 330;             // qkv row stride (floats)
constexpr int BDIM = 512;

// ---------------- smem layout (bytes) ----------------
constexpr int OFF_X    = 0;                          // 336*200*2 = 134400
constexpr int OFF_W    = OFF_X + NB * KPAD * 2;      // 48*200*2  = 19200
constexpr int OFF_BIAS = OFF_W + 48 * KPAD * 2;      // 153600
constexpr int OFF_QKV  = OFF_BIAS + 256;             // 153856
constexpr int SMEM_TOTAL = OFF_QKV + 48 * NPADQ * 4; // 217216

__device__ __forceinline__ void mma16816(float* c, const uint32_t* a,
                                         uint32_t b0, uint32_t b1) {
    asm volatile(
        "mma.sync.aligned.m16n8k16.row.col.f32.bf16.bf16.f32 "
        "{%0,%1,%2,%3}, {%4,%5,%6,%7}, {%8,%9}, {%0,%1,%2,%3};"
        : "+f"(c[0]), "+f"(c[1]), "+f"(c[2]), "+f"(c[3])
        : "r"(a[0]), "r"(a[1]), "r"(a[2]), "r"(a[3]), "r"(b0), "r"(b1));
}
__device__ __forceinline__ void ldsm_x4(uint32_t* r, uint32_t addr) {
    asm volatile("ldmatrix.sync.aligned.m8n8.x4.shared.b16 {%0,%1,%2,%3}, [%4];"
        : "=r"(r[0]), "=r"(r[1]), "=r"(r[2]), "=r"(r[3]) : "r"(addr));
}
__device__ __forceinline__ uint32_t smem_u32(const void* p) {
    uint32_t a;
    asm("{ .reg .u64 t; cvta.to.shared.u64 t, %1; cvt.u32.u64 %0, t; }" : "=r"(a) : "l"(p));
    return a;
}
__device__ __forceinline__ uint32_t pack_bf16x2(float lo_f, float hi_f) {
    __nv_bfloat162 h = __floats2bfloat162_rn(lo_f, hi_f);
    return *reinterpret_cast<uint32_t*>(&h);
}

__global__ __launch_bounds__(BDIM, 1)
void attn_kernel(const float* __restrict__ x,
                 const float* __restrict__ Wq, const float* __restrict__ bq,
                 const float* __restrict__ Wk, const float* __restrict__ bk,
                 const float* __restrict__ Wv, const float* __restrict__ bv,
                 float* __restrict__ out)
{
    extern __shared__ char smem[];
    __nv_bfloat16* Xs = reinterpret_cast<__nv_bfloat16*>(smem + OFF_X);   // [NB][KPAD]
    __nv_bfloat16* Ws = reinterpret_cast<__nv_bfloat16*>(smem + OFF_W);   // [48][KPAD]
    float*  bsh = reinterpret_cast<float*>(smem + OFF_BIAS);              // [48]
    float*  qkv = reinterpret_cast<float*>(smem + OFF_QKV);               // [48][NPADQ]

    const int b    = blockIdx.z;
    const int h0   = blockIdx.y * TH;
    const int w0   = blockIdx.x * TW;
    const int tid  = threadIdx.x;
    const int wid  = tid >> 5;
    const int lane = tid & 31;

    // ------------------------------------------------------------------
    // Phase 0: X halo tile -> smem, reflection pad(1), bf16 hi/lo split.
    // Xs row = point, cols: [0:64)=Xhi, [64:128)=Xhi, [128:192)=Xlo.
    // ------------------------------------------------------------------
    const float* xb = x + (size_t)b * C * H * Wd;
    for (int i = tid; i < (C / 2) * NPT; i += BDIM) {
        int cp = i / NPT;
        int p  = i - cp * NPT;
        int c  = cp * 2;
        int py = p / WP;
        int px = p - py * WP;
        int gy = h0 + py - 1;
        gy = (gy < 0) ? -gy : ((gy >= H) ? (2 * H - 2 - gy) : gy);
        int gx = w0 + px - 1;
        gx = (gx < 0) ? -gx : ((gx >= Wd) ? (2 * Wd - 2 - gx) : gx);
        float x0 = xb[(c + 0) * H * Wd + gy * Wd + gx];
        float x1 = xb[(c + 1) * H * Wd + gy * Wd + gx];
        __nv_bfloat16 h0b = __float2bfloat16(x0);
        __nv_bfloat16 h1b = __float2bfloat16(x1);
        float l0 = x0 - __bfloat162float(h0b);
        float l1 = x1 - __bfloat162float(h1b);
        uint32_t hi2 = ((uint32_t)*reinterpret_cast<uint16_t*>(&h0b)) |
                       ((uint32_t)*reinterpret_cast<uint16_t*>(&h1b) << 16);
        uint32_t lo2 = pack_bf16x2(l0, l1);
        uint32_t* row = reinterpret_cast<uint32_t*>(Xs + p * KPAD);
        row[c / 2]         = hi2;
        row[(64 + c) / 2]  = hi2;
        row[(128 + c) / 2] = lo2;
    }
    // zero pad rows 324..335 (cols 0..191)
    for (int i = tid; i < (NB - NPT) * (KT / 2); i += BDIM) {
        int p  = NPT + i / (KT / 2);
        int c2 = i % (KT / 2);
        reinterpret_cast<uint32_t*>(Xs + p * KPAD)[c2] = 0u;
    }

    // softmax-phase fixed assignment: 2 threads/pixel, 8 channels each
    const int px_  = tid & 255;
    const int half = tid >> 8;
    const int ty   = px_ >> 4;
    const int tx   = px_ & 15;
    const int ip   = (ty + 1) * WP + (tx + 1);
    const int tap0 = ty * WP + tx;
    float* outp = out + (((size_t)b * C) * H + (h0 + ty)) * Wd + (w0 + tx);

    // GEMM warp assignment: 12 warps = 3 m-tiles x 4 n-group strides
    const int mtile  = wid >> 2;          // 0..3 (3 = inactive)
    const int ngrp   = wid & 3;
    const bool gemm_w = (wid < 12);
    const int r0 = mtile * 16 + (lane >> 2);
    const int r1 = r0 + 8;

    // ldmatrix lane-address components (shared by A and B patterns):
    // matrix idx = lane>>3: 0:(row+0,k+0) 1:(row+8,k+0) 2:(row+0,k+8) 3:(row+8,k+8)
    const int lrow = (lane & 7) + ((lane >> 3) & 1) * 8;
    const int lkof = (lane >> 4) * 8;
    const uint32_t xs_base = smem_u32(Xs);
    const uint32_t ws_base = smem_u32(Ws);
    const uint32_t aAddr0  = ws_base + (uint32_t)((mtile * 16 + lrow) * (KPAD * 2) + lkof * 2);

    // ------------------------------------------------------------------
    // chunk loop: 4 chunks of 16 channels. rows: [q16 | k16 | v16]
    // ------------------------------------------------------------------
    for (int ck = 0; ck < 4; ++ck) {
        const int c0 = ck * OC;

        // Phase A: chunk weights -> Ws (segments: hi | lo | hi), bias -> bsh
        for (int i = tid; i < 48 * 32; i += BDIM) {
            int m  = i >> 5;
            int cp = i & 31;
            int c  = cp * 2;
            int mat = m >> 4;
            int ch  = c0 + (m & 15);
            const float* Wsrc = (mat == 0) ? Wq : (mat == 1) ? Wk : Wv;
            float2 w = *reinterpret_cast<const float2*>(Wsrc + ch * C + c);
            __nv_bfloat16 h0b = __float2bfloat16(w.x);
            __nv_bfloat16 h1b = __float2bfloat16(w.y);
            float l0 = w.x - __bfloat162float(h0b);
            float l1 = w.y - __bfloat162float(h1b);
            uint32_t hi2 = ((uint32_t)*reinterpret_cast<uint16_t*>(&h0b)) |
                           ((uint32_t)*reinterpret_cast<uint16_t*>(&h1b) << 16);
            uint32_t lo2 = pack_bf16x2(l0, l1);
            uint32_t* row = reinterpret_cast<uint32_t*>(Ws + m * KPAD);
            row[c / 2]         = hi2;
            row[(64 + c) / 2]  = lo2;
            row[(128 + c) / 2] = hi2;
        }
        if (tid < 48) {
            int mat = tid >> 4;
            int ch  = c0 + (tid & 15);
            bsh[tid] = ((mat == 0) ? bq : (mat == 1) ? bk : bv)[ch];
        }
        __syncthreads();   // Ws/bias ready; prev softmax done -> qkv reusable

        // Phase B: HMMA GEMM  qkv[48][336] = Ws[48][192] * Xs^T (ldmatrix feeds)
        if (gemm_w) {
            float acc[12][4];
            {
                float b0v = bsh[r0], b1v = bsh[r1];
                #pragma unroll
                for (int i = 0; i < 12; ++i) {
                    acc[i][0] = b0v; acc[i][1] = b0v;
                    acc[i][2] = b1v; acc[i][3] = b1v;
                }
            }
            #pragma unroll 1
            for (int s = 0; s < 12; ++s) {
                const uint32_t kboff = (uint32_t)(s * 32);   // 16 bf16 = 32 B
                uint32_t a[4];
                ldsm_x4(a, aAddr0 + kboff);
                #pragma unroll
                for (int i = 0; i < 6; ++i) {
                    const int g = ngrp + i * 4;
                    if (g < NG) {
                        // B x4: r0=n(g*16+0..7)k0-7, r1=n+8 k0-7, r2=n k8-15, r3=n+8 k8-15
                        uint32_t br[4];
                        uint32_t baddr = xs_base +
                            (uint32_t)((g * 16 + lrow) * (KPAD * 2) + lkof * 2) + kboff;
                        ldsm_x4(br, baddr);
                        mma16816(acc[2 * i + 0], a, br[0], br[2]);
                        mma16816(acc[2 * i + 1], a, br[1], br[3]);
                    }
                }
            }
            // store D -> qkv; skip padded cols >= 328
            #pragma unroll
            for (int i = 0; i < 6; ++i) {
                const int g = ngrp + i * 4;
                if (g < NG) {
                    int col0 = g * 16 + (lane & 3) * 2;
                    *reinterpret_cast<float2*>(qkv + r0 * NPADQ + col0) =
                        make_float2(acc[2 * i][0], acc[2 * i][1]);
                    *reinterpret_cast<float2*>(qkv + r1 * NPADQ + col0) =
                        make_float2(acc[2 * i][2], acc[2 * i][3]);
                    if (g < NG - 1) {
                        int col1 = col0 + 8;
                        *reinterpret_cast<float2*>(qkv + r0 * NPADQ + col1) =
                            make_float2(acc[2 * i + 1][0], acc[2 * i + 1][1]);
                        *reinterpret_cast<float2*>(qkv + r1 * NPADQ + col1) =
                            make_float2(acc[2 * i + 1][2], acc[2 * i + 1][3]);
                    }
                }
            }
        }
        __syncthreads();   // qkv ready

        // Phase C: per-pixel, per-channel 9-tap softmax
        #pragma unroll 1
        for (int r = 0; r < 8; ++r) {
            const int ch = half * 8 + r;                    // 0..15
            const float q = qkv[ch * NPADQ + ip];
            const float* kr = qkv + (16 + ch) * NPADQ;
            const float* vr = qkv + (32 + ch) * NPADQ;
            float s = 0.f, acc = 0.f;
            #pragma unroll
            for (int t = 0; t < 9; ++t) {
                int pp = tap0 + (t / 3) * WP + (t % 3);
                float e = __expf(q * kr[pp]);
                s   += e;
                acc  = fmaf(e, vr[pp], acc);
            }
            outp[(size_t)(c0 + ch) * H * Wd] = __fdividef(acc, s);
        }
        // next iteration's post-A __syncthreads orders qkv reuse
    }
}

extern "C" void kernel_launch(void* const* d_in, const int* in_sizes, int n_in,
                              void* d_out, int out_size)
{
    const float* x  = (const float*)d_in[0];
    const float* Wq = (const float*)d_in[1];
    const float* bq = (const float*)d_in[2];
    const float* Wk = (const float*)d_in[3];
    const float* bk = (const float*)d_in[4];
    const float* Wv = (const float*)d_in[5];
    const float* bv = (const float*)d_in[6];
    float* out = (float*)d_out;

    cudaFuncSetAttribute(attn_kernel, cudaFuncAttributeMaxDynamicSharedMemorySize,
                         SMEM_TOTAL);
    dim3 grid(Wd / TW, H / TH, Bn);   // (12, 12, 4)
    attn_kernel<<<grid, BDIM, SMEM_TOTAL>>>(x, Wq, bq, Wk, bk, Wv, bv, out);
}